// round 5
// baseline (speedup 1.0000x reference)
#include <cuda_runtime.h>
#include <math.h>

#define H_IN   14
#define W_IN   14
#define HP     12
#define WP     12
#define ISZ    144
#define OSZ    16
#define NPOS   1152
#define RST    145          // row stride: odd -> conflict-free column access
#define EPSF   1e-9f

__global__ void __launch_bounds__(1024, 1)
capsconv_em_kernel(const float* __restrict__ pose_in,   // [8,14,14,256]
                   const float* __restrict__ act_in,    // [8,14,14,16]
                   const float* __restrict__ w,         // [144,16,16]
                   const float* __restrict__ beta_v,    // [16]
                   const float* __restrict__ beta_a,    // [16]
                   float* __restrict__ out)             // pose[1152*256] ++ act[1152*16]
{
    __shared__ float poseS[ISZ * 16];        //  9216 B
    __shared__ float actS[ISZ];              //   576 B
    __shared__ float rpS[OSZ * RST];         //  9280 B
    __shared__ float zpart[2][OSZ * RST];    // 18560 B
    __shared__ float lsumX[2][OSZ];          //   128 B
    __shared__ float clS[OSZ];               //    64 B

    const int tid = threadIdx.x;
    const int n   = blockIdx.x;
    const int b   = n / (HP * WP);
    const int rem = n % (HP * WP);
    const int y   = rem / WP;
    const int x   = rem % WP;

    // ---- Stage pose patch + activations (coalesced) ----
    for (int idx = tid; idx < ISZ * 4; idx += 1024) {
        int i  = idx >> 2;
        int p4 = idx & 3;
        int pos = i >> 4, cc = i & 15;
        int ky = pos / 3, kx = pos % 3;
        const float4* src = reinterpret_cast<const float4*>(
            pose_in + ((((b * H_IN) + y + ky) * W_IN + (x + kx)) * 256 + cc * 16));
        reinterpret_cast<float4*>(poseS)[i * 4 + p4] = src[p4];
    }
    for (int i = tid; i < ISZ; i += 1024) {
        int pos = i >> 4, cc = i & 15;
        int ky = pos / 3, kx = pos % 3;
        actS[i] = act_in[(((b * H_IN) + y + ky) * W_IN + (x + kx)) * OSZ + cc];
    }
    __syncthreads();

    // ---- rp init for iteration 0 ----
    for (int idx = tid; idx < OSZ * ISZ; idx += 1024) {
        int oo = idx / ISZ;
        int i  = idx - oo * ISZ;
        rpS[oo * RST + i] = actS[i] * 0.0625f;
    }

    // ---- Thread mapping ----
    const int lane = tid & 31;
    const int wid  = tid >> 5;
    const int o    = wid & 15;      // output capsule (2 warps per o)
    const int h    = wid >> 4;      // warp-half: p dims [8h, 8h+8)
    const int g    = lane >> 4;     // p-group within warp
    const int c    = lane & 15;     // i = c + 16*ii
    const int pg   = h * 2 + g;     // pose row (4 p dims)

    // ---- Vote transform into registers: vt[ii] = pose[i][pg][:] @ w[i][o] ----
    float4 vt[9];
    #pragma unroll
    for (int ii = 0; ii < 9; ++ii) {
        const int i = c + (ii << 4);
        float4 p = reinterpret_cast<const float4*>(poseS)[i * 4 + pg];
        const float4* wr = reinterpret_cast<const float4*>(w) + (i * 16 + o) * 4;
        float4 w0 = wr[0];
        float4 r;
        r.x = p.x * w0.x; r.y = p.x * w0.y; r.z = p.x * w0.z; r.w = p.x * w0.w;
        float4 w1 = wr[1];
        r.x = fmaf(p.y, w1.x, r.x); r.y = fmaf(p.y, w1.y, r.y);
        r.z = fmaf(p.y, w1.z, r.z); r.w = fmaf(p.y, w1.w, r.w);
        float4 w2 = wr[2];
        r.x = fmaf(p.z, w2.x, r.x); r.y = fmaf(p.z, w2.y, r.y);
        r.z = fmaf(p.z, w2.z, r.z); r.w = fmaf(p.z, w2.w, r.w);
        float4 w3 = wr[3];
        r.x = fmaf(p.w, w3.x, r.x); r.y = fmaf(p.w, w3.y, r.y);
        r.z = fmaf(p.w, w3.z, r.z); r.w = fmaf(p.w, w3.w, r.w);
        vt[ii] = r;
    }
    const float bv = beta_v[o];
    const float ba = beta_a[o];
    const float* rpo = rpS + o * RST;
    __syncthreads();   // rp ready, staging done

    for (int it = 0; it < 3; ++it) {
        // ---- M-step: single-pass moments (votes in registers, rp broadcast) ----
        float m0=0.f,m1=0.f,m2=0.f,m3=0.f;
        float s0=0.f,s1=0.f,s2=0.f,s3=0.f;
        float rs=0.f;
        #pragma unroll
        for (int ii = 0; ii < 9; ++ii) {
            float rp = rpo[c + (ii << 4)];
            float4 v = vt[ii];
            float tx = rp * v.x, ty = rp * v.y, tz = rp * v.z, tw = rp * v.w;
            m0 += tx;  s0 = fmaf(tx, v.x, s0);
            m1 += ty;  s1 = fmaf(ty, v.y, s1);
            m2 += tz;  s2 = fmaf(tz, v.z, s2);
            m3 += tw;  s3 = fmaf(tw, v.w, s3);
            rs += rp;
        }
        // Butterfly over c (16 lanes) -> full sums over all 144 i
        #pragma unroll
        for (int off = 1; off < 16; off <<= 1) {
            m0 += __shfl_xor_sync(0xffffffffu, m0, off);
            m1 += __shfl_xor_sync(0xffffffffu, m1, off);
            m2 += __shfl_xor_sync(0xffffffffu, m2, off);
            m3 += __shfl_xor_sync(0xffffffffu, m3, off);
            s0 += __shfl_xor_sync(0xffffffffu, s0, off);
            s1 += __shfl_xor_sync(0xffffffffu, s1, off);
            s2 += __shfl_xor_sync(0xffffffffu, s2, off);
            s3 += __shfl_xor_sync(0xffffffffu, s3, off);
            rs += __shfl_xor_sync(0xffffffffu, rs, off);
        }
        const float inv_r = __fdividef(1.0f, rs + EPSF);
        const float me0 = m0 * inv_r, me1 = m1 * inv_r;
        const float me2 = m2 * inv_r, me3 = m3 * inv_r;
        float e0 = fmaf(me0, fmaf(me0, rs, -2.0f * m0), s0);
        float e1 = fmaf(me1, fmaf(me1, rs, -2.0f * m1), s1);
        float e2 = fmaf(me2, fmaf(me2, rs, -2.0f * m2), s2);
        float e3 = fmaf(me3, fmaf(me3, rs, -2.0f * m3), s3);
        float v0 = fmaxf(e0, 0.f) * inv_r, v1 = fmaxf(e1, 0.f) * inv_r;
        float v2 = fmaxf(e2, 0.f) * inv_r, v3 = fmaxf(e3, 0.f) * inv_r;
        float l8 = (__logf(sqrtf(v0) + EPSF) + __logf(sqrtf(v1) + EPSF))
                 + (__logf(sqrtf(v2) + EPSF) + __logf(sqrtf(v3) + EPSF));
        l8 += __shfl_xor_sync(0xffffffffu, l8, 16);      // sum over this warp's 8 p
        if (lane == 0) lsumX[h][o] = l8;
        __syncthreads();
        const float lsum = l8 + lsumX[1 - h][o];         // all 16 p

        const float inv_temp = 1.0f + (float)it;
        const float cost = fmaf(16.0f, bv, lsum) * rs;
        const float a = __fdividef(1.0f, 1.0f + __expf(-inv_temp * (ba - cost)));

        if (it == 2) {
            if (c == 0) {
                *reinterpret_cast<float4*>(out + n * 256 + o * 16 + pg * 4) =
                    make_float4(me0, me1, me2, me3);
            }
            if (wid < 16 && lane == 0)
                out[NPOS * 256 + n * OSZ + o] = a;
            return;
        }

        const float iv0 = __fdividef(1.0f, 2.0f * v0 + EPSF);
        const float iv1 = __fdividef(1.0f, 2.0f * v1 + EPSF);
        const float iv2 = __fdividef(1.0f, 2.0f * v2 + EPSF);
        const float iv3 = __fdividef(1.0f, 2.0f * v3 + EPSF);
        if (h == 0 && lane == 0)
            clS[o] = __logf(a + EPSF) - lsum;            // z = clS[o] - acc_total

        // ---- E-step part 1: this warp's 8-p distance partial per i ----
        #pragma unroll
        for (int ii = 0; ii < 9; ++ii) {
            float4 v = vt[ii];
            float dx = v.x - me0, dy = v.y - me1;
            float dz = v.z - me2, dw = v.w - me3;
            float acc = dx * dx * iv0;
            acc = fmaf(dy * dy, iv1, acc);
            acc = fmaf(dz * dz, iv2, acc);
            acc = fmaf(dw * dw, iv3, acc);
            acc += __shfl_xor_sync(0xffffffffu, acc, 16);  // + g-partner's 4 p
            if (g == 0)
                zpart[h][o * RST + c + (ii << 4)] = acc;
        }
        __syncthreads();   // zpart + clS ready

        // ---- E-step part 2: softmax over o, fold act -> rp ----
        if (tid < 2 * ISZ) {
            const int i  = tid >> 1;
            const int g2 = tid & 1;
            float zz[8];
            float zmax = -1e30f;
            #pragma unroll
            for (int j = 0; j < 8; ++j) {
                int oo = (j << 1) + g2;
                float acc = zpart[0][oo * RST + i] + zpart[1][oo * RST + i];
                float z = clS[oo] - acc;
                zz[j] = z;
                zmax = fmaxf(zmax, z);
            }
            zmax = fmaxf(zmax, __shfl_xor_sync(0xffffffffu, zmax, 1));
            float es = 0.f;
            #pragma unroll
            for (int j = 0; j < 8; ++j) { zz[j] = __expf(zz[j] - zmax); es += zz[j]; }
            es += __shfl_xor_sync(0xffffffffu, es, 1);
            const float f = __fdividef(actS[i], es);       // softmax * act
            #pragma unroll
            for (int j = 0; j < 8; ++j)
                rpS[((j << 1) + g2) * RST + i] = zz[j] * f;
        }
        __syncthreads();   // rp ready for next M-step
    }
}

extern "C" void kernel_launch(void* const* d_in, const int* in_sizes, int n_in,
                              void* d_out, int out_size)
{
    const float* pose_in = (const float*)d_in[0];
    const float* act_in  = (const float*)d_in[1];
    const float* w       = (const float*)d_in[2];
    const float* bv      = (const float*)d_in[3];
    const float* ba      = (const float*)d_in[4];
    float* out           = (float*)d_out;

    capsconv_em_kernel<<<NPOS, 1024>>>(pose_in, act_in, w, bv, ba, out);
}

// round 8
// speedup vs baseline: 2.0484x; 2.0484x over previous
#include <cuda_runtime.h>
#include <math.h>

#define H_IN   14
#define W_IN   14
#define HP     12
#define WP     12
#define ISZ    144
#define OSZ    16
#define NPOS   1152
#define VSTRIDE 260        // votes i-stride: 260 % 32 == 4 -> conflict-free LDS128
#define RST    145         // rp/z row stride: odd -> conflict-free column access
#define EPSF   1e-9f

struct Smem {
    float votes[ISZ * VSTRIDE];   // [i][o*16+p]    149760 B
    float poseS[ISZ * 16];        //                  9216 B
    float actS[ISZ];              //                   576 B
    float rpT[OSZ * RST];         // [o][i] rr*act    9280 B
    float zS[OSZ * RST];          // [o][i] log-lik   9280 B
};                                 // total ~178 KB

__global__ void __launch_bounds__(512, 1)
capsconv_em_kernel(const float* __restrict__ pose_in,   // [8,14,14,256]
                   const float* __restrict__ act_in,    // [8,14,14,16]
                   const float* __restrict__ w,         // [144,16,16]
                   const float* __restrict__ beta_v,    // [16]
                   const float* __restrict__ beta_a,    // [16]
                   float* __restrict__ out)             // pose[1152*256] ++ act[1152*16]
{
    extern __shared__ char smem_raw[];
    Smem& sm = *reinterpret_cast<Smem*>(smem_raw);

    const int tid = threadIdx.x;
    const int n   = blockIdx.x;
    const int b   = n / (HP * WP);
    const int rem = n % (HP * WP);
    const int y   = rem / WP;
    const int x   = rem % WP;

    // ---- Stage pose patch + activations (coalesced) ----
    for (int idx = tid; idx < ISZ * 4; idx += 512) {
        int i  = idx >> 2;
        int p4 = idx & 3;
        int pos = i >> 4, cc = i & 15;
        int ky = pos / 3, kx = pos % 3;
        const float4* src = reinterpret_cast<const float4*>(
            pose_in + ((((b * H_IN) + y + ky) * W_IN + (x + kx)) * 256 + cc * 16));
        reinterpret_cast<float4*>(sm.poseS)[i * 4 + p4] = src[p4];
    }
    for (int i = tid; i < ISZ; i += 512) {
        int pos = i >> 4, cc = i & 15;
        int ky = pos / 3, kx = pos % 3;
        sm.actS[i] = act_in[(((b * H_IN) + y + ky) * W_IN + (x + kx)) * OSZ + cc];
    }
    __syncthreads();

    // ---- rp init (iteration 0: rr uniform) ----
    for (int idx = tid; idx < OSZ * ISZ; idx += 512) {
        int oo = idx / ISZ;
        int i  = idx - oo * ISZ;
        sm.rpT[oo * RST + i] = sm.actS[i] * 0.0625f;
    }

    // ---- Vote transform: votes[i][o][pr,:] = pose[i][pr,:] @ w[i][o] ----
    for (int pair = tid; pair < ISZ * OSZ; pair += 512) {
        int i = pair >> 4;
        const float4* wrow = reinterpret_cast<const float4*>(w + pair * 16);
        float4 w0 = wrow[0], w1 = wrow[1], w2 = wrow[2], w3 = wrow[3];
        const float* ps = sm.poseS + i * 16;
        float4* vout = reinterpret_cast<float4*>(sm.votes + i * VSTRIDE + (pair & 15) * 16);
        #pragma unroll
        for (int pr = 0; pr < 4; pr++) {
            float a0 = ps[pr * 4 + 0], a1 = ps[pr * 4 + 1];
            float a2 = ps[pr * 4 + 2], a3 = ps[pr * 4 + 3];
            float4 r;
            r.x = fmaf(a0, w0.x, fmaf(a1, w1.x, fmaf(a2, w2.x, a3 * w3.x)));
            r.y = fmaf(a0, w0.y, fmaf(a1, w1.y, fmaf(a2, w2.y, a3 * w3.y)));
            r.z = fmaf(a0, w0.z, fmaf(a1, w1.z, fmaf(a2, w2.z, a3 * w3.z)));
            r.w = fmaf(a0, w0.w, fmaf(a1, w1.w, fmaf(a2, w2.w, a3 * w3.w)));
            vout[pr] = r;
        }
    }

    // ---- EM mapping: warp <-> o ; lane = pg*8 + chunk ; i = chunk + 8*ii ----
    const int lane  = tid & 31;
    const int o     = tid >> 5;
    const int pg    = lane >> 3;    // this lane's 4 p dims: [4pg, 4pg+4)
    const int chunk = lane & 7;
    const float bv  = beta_v[o];
    const float ba  = beta_a[o];
    const float* vbase = sm.votes + o * 16 + pg * 4;
    const float* rpo   = sm.rpT + o * RST;
    __syncthreads();   // rp + votes ready

    for (int it = 0; it < 3; ++it) {
        // ---- M-step: single-pass moments over i-strip ----
        float m0=0.f,m1=0.f,m2=0.f,m3=0.f;
        float s0=0.f,s1=0.f,s2=0.f,s3=0.f;
        float rs=0.f;
        #pragma unroll 6
        for (int ii = 0; ii < 18; ++ii) {
            const int i = chunk + (ii << 3);
            float rp = rpo[i];
            float4 v = *reinterpret_cast<const float4*>(vbase + i * VSTRIDE);
            float tx = rp * v.x, ty = rp * v.y, tz = rp * v.z, tw = rp * v.w;
            m0 += tx;  s0 = fmaf(tx, v.x, s0);
            m1 += ty;  s1 = fmaf(ty, v.y, s1);
            m2 += tz;  s2 = fmaf(tz, v.z, s2);
            m3 += tw;  s3 = fmaf(tw, v.w, s3);
            rs += rp;
        }
        // reduce over chunk (8 lanes)
        #pragma unroll
        for (int off = 1; off < 8; off <<= 1) {
            m0 += __shfl_xor_sync(0xffffffffu, m0, off);
            m1 += __shfl_xor_sync(0xffffffffu, m1, off);
            m2 += __shfl_xor_sync(0xffffffffu, m2, off);
            m3 += __shfl_xor_sync(0xffffffffu, m3, off);
            s0 += __shfl_xor_sync(0xffffffffu, s0, off);
            s1 += __shfl_xor_sync(0xffffffffu, s1, off);
            s2 += __shfl_xor_sync(0xffffffffu, s2, off);
            s3 += __shfl_xor_sync(0xffffffffu, s3, off);
            rs += __shfl_xor_sync(0xffffffffu, rs, off);
        }
        const float inv_r = __fdividef(1.0f, rs + EPSF);
        const float me0 = m0 * inv_r, me1 = m1 * inv_r;
        const float me2 = m2 * inv_r, me3 = m3 * inv_r;
        float e0 = fmaf(me0, fmaf(me0, rs, -2.0f * m0), s0);
        float e1 = fmaf(me1, fmaf(me1, rs, -2.0f * m1), s1);
        float e2 = fmaf(me2, fmaf(me2, rs, -2.0f * m2), s2);
        float e3 = fmaf(me3, fmaf(me3, rs, -2.0f * m3), s3);
        float v0 = fmaxf(e0, 0.f) * inv_r, v1 = fmaxf(e1, 0.f) * inv_r;
        float v2 = fmaxf(e2, 0.f) * inv_r, v3 = fmaxf(e3, 0.f) * inv_r;
        float l4 = (__logf(sqrtf(v0) + EPSF) + __logf(sqrtf(v1) + EPSF))
                 + (__logf(sqrtf(v2) + EPSF) + __logf(sqrtf(v3) + EPSF));
        // reduce over pg (4 groups) -> lsum over all 16 p
        float lsum = l4;
        lsum += __shfl_xor_sync(0xffffffffu, lsum, 8);
        lsum += __shfl_xor_sync(0xffffffffu, lsum, 16);

        const float inv_temp = 1.0f + (float)it;
        const float cost = fmaf(16.0f, bv, lsum) * rs;
        const float a = __fdividef(1.0f, 1.0f + __expf(-inv_temp * (ba - cost)));

        if (it == 2) {
            if (chunk == 0) {
                *reinterpret_cast<float4*>(out + n * 256 + o * 16 + pg * 4) =
                    make_float4(me0, me1, me2, me3);
            }
            if (lane == 0)
                out[NPOS * 256 + n * OSZ + o] = a;
            return;
        }

        const float iv0 = __fdividef(1.0f, 2.0f * v0 + EPSF);
        const float iv1 = __fdividef(1.0f, 2.0f * v1 + EPSF);
        const float iv2 = __fdividef(1.0f, 2.0f * v2 + EPSF);
        const float iv3 = __fdividef(1.0f, 2.0f * v3 + EPSF);
        const float zc  = __logf(a + EPSF) - lsum;     // z = zc - distance

        // ---- E-step part 1: distances from this warp's own strip ----
        #pragma unroll 3
        for (int ii = 0; ii < 18; ++ii) {
            const int i = chunk + (ii << 3);
            float4 v = *reinterpret_cast<const float4*>(vbase + i * VSTRIDE);
            float dx = v.x - me0, dy = v.y - me1;
            float dz = v.z - me2, dw = v.w - me3;
            float acc = dx * dx * iv0;
            acc = fmaf(dy * dy, iv1, acc);
            acc = fmaf(dz * dz, iv2, acc);
            acc = fmaf(dw * dw, iv3, acc);
            acc += __shfl_xor_sync(0xffffffffu, acc, 8);
            acc += __shfl_xor_sync(0xffffffffu, acc, 16);   // sum over 16 p
            if (pg == 0)
                sm.zS[o * RST + i] = zc - acc;
        }
        __syncthreads();   // z ready

        // ---- E-step part 2: softmax over o, fold act -> rp ----
        if (tid < 2 * ISZ) {
            const int i  = tid >> 1;
            const int g2 = tid & 1;
            float zz[8];
            float zmax = -1e30f;
            #pragma unroll
            for (int j = 0; j < 8; ++j) {
                float z = sm.zS[((j << 1) + g2) * RST + i];
                zz[j] = z;
                zmax = fmaxf(zmax, z);
            }
            zmax = fmaxf(zmax, __shfl_xor_sync(0xffffffffu, zmax, 1));
            float es = 0.f;
            #pragma unroll
            for (int j = 0; j < 8; ++j) { zz[j] = __expf(zz[j] - zmax); es += zz[j]; }
            es += __shfl_xor_sync(0xffffffffu, es, 1);
            const float f = __fdividef(sm.actS[i], es);   // softmax * act
            #pragma unroll
            for (int j = 0; j < 8; ++j)
                sm.rpT[((j << 1) + g2) * RST + i] = zz[j] * f;
        }
        __syncthreads();   // rp ready for next M-step
    }
}

extern "C" void kernel_launch(void* const* d_in, const int* in_sizes, int n_in,
                              void* d_out, int out_size)
{
    const float* pose_in = (const float*)d_in[0];
    const float* act_in  = (const float*)d_in[1];
    const float* w       = (const float*)d_in[2];
    const float* bv      = (const float*)d_in[3];
    const float* ba      = (const float*)d_in[4];
    float* out           = (float*)d_out;

    const int smem = (int)sizeof(Smem);
    cudaFuncSetAttribute(capsconv_em_kernel,
                         cudaFuncAttributeMaxDynamicSharedMemorySize, smem);
    capsconv_em_kernel<<<NPOS, 512, smem>>>(pose_in, act_in, w, bv, ba, out);
}

// round 9
// speedup vs baseline: 2.6903x; 1.3133x over previous
#include <cuda_runtime.h>
#include <cuda_fp16.h>
#include <math.h>

#define H_IN   14
#define W_IN   14
#define HP     12
#define WP     12
#define ISZ    144
#define OSZ    16
#define NPOS   1152
#define VSH2   136         // votes stride per i, in half2 units (272 halfs = 544 B)
#define RST    145         // rp/z row stride (floats): odd -> conflict-free columns
#define EPSF   1e-9f

struct Smem {
    __half2 votes[ISZ * VSH2];    // [i][o*8 + pp]   78336 B  (8B aligned, first)
    float poseS[ISZ * 16];        //                  9216 B
    float actS[ISZ];              //                   576 B
    float rpT[OSZ * RST];         // [o][i] rr*act    9280 B
    float zS[OSZ * RST];          // [o][i] log-lik   9280 B
};                                 // total 106688 B -> 2 CTAs/SM

__global__ void __launch_bounds__(512, 2)
capsconv_em_kernel(const float* __restrict__ pose_in,   // [8,14,14,256]
                   const float* __restrict__ act_in,    // [8,14,14,16]
                   const float* __restrict__ w,         // [144,16,16]
                   const float* __restrict__ beta_v,    // [16]
                   const float* __restrict__ beta_a,    // [16]
                   float* __restrict__ out)             // pose[1152*256] ++ act[1152*16]
{
    extern __shared__ char smem_raw[];
    Smem& sm = *reinterpret_cast<Smem*>(smem_raw);

    const int tid = threadIdx.x;
    const int n   = blockIdx.x;
    const int b   = n / (HP * WP);
    const int rem = n % (HP * WP);
    const int y   = rem / WP;
    const int x   = rem % WP;

    // ---- Stage pose patch + activations (coalesced) ----
    for (int idx = tid; idx < ISZ * 4; idx += 512) {
        int i  = idx >> 2;
        int p4 = idx & 3;
        int pos = i >> 4, cc = i & 15;
        int ky = pos / 3, kx = pos % 3;
        const float4* src = reinterpret_cast<const float4*>(
            pose_in + ((((b * H_IN) + y + ky) * W_IN + (x + kx)) * 256 + cc * 16));
        reinterpret_cast<float4*>(sm.poseS)[i * 4 + p4] = src[p4];
    }
    for (int i = tid; i < ISZ; i += 512) {
        int pos = i >> 4, cc = i & 15;
        int ky = pos / 3, kx = pos % 3;
        sm.actS[i] = act_in[(((b * H_IN) + y + ky) * W_IN + (x + kx)) * OSZ + cc];
    }
    __syncthreads();

    // ---- rp init (iteration 0: rr uniform) ----
    for (int idx = tid; idx < OSZ * ISZ; idx += 512) {
        int oo = idx / ISZ;
        int i  = idx - oo * ISZ;
        sm.rpT[oo * RST + i] = sm.actS[i] * 0.0625f;
    }

    // ---- Vote transform: votes[i][o][pr,:] = pose[i][pr,:] @ w[i][o], fp16 store ----
    for (int pair = tid; pair < ISZ * OSZ; pair += 512) {
        int i  = pair >> 4;
        int oo = pair & 15;
        const float4* wrow = reinterpret_cast<const float4*>(w + pair * 16);
        float4 w0 = wrow[0], w1 = wrow[1], w2 = wrow[2], w3 = wrow[3];
        const float* ps = sm.poseS + i * 16;
        #pragma unroll
        for (int pr = 0; pr < 4; pr++) {
            float a0 = ps[pr * 4 + 0], a1 = ps[pr * 4 + 1];
            float a2 = ps[pr * 4 + 2], a3 = ps[pr * 4 + 3];
            float rx = fmaf(a0, w0.x, fmaf(a1, w1.x, fmaf(a2, w2.x, a3 * w3.x)));
            float ry = fmaf(a0, w0.y, fmaf(a1, w1.y, fmaf(a2, w2.y, a3 * w3.y)));
            float rz = fmaf(a0, w0.z, fmaf(a1, w1.z, fmaf(a2, w2.z, a3 * w3.z)));
            float rw = fmaf(a0, w0.w, fmaf(a1, w1.w, fmaf(a2, w2.w, a3 * w3.w)));
            __half2 h0 = __float22half2_rn(make_float2(rx, ry));
            __half2 h1 = __float22half2_rn(make_float2(rz, rw));
            uint2 st;
            st.x = *reinterpret_cast<unsigned int*>(&h0);
            st.y = *reinterpret_cast<unsigned int*>(&h1);
            *reinterpret_cast<uint2*>(sm.votes + i * VSH2 + oo * 8 + pr * 2) = st;
        }
    }

    // ---- EM mapping: warp <-> o ; lane = c*4 + pg ; i = c + 8*ii ----
    const int lane = tid & 31;
    const int o    = tid >> 5;
    const int pg   = lane & 3;      // this lane's 4 p dims: [4pg, 4pg+4)
    const int c    = lane >> 2;     // i-chunk
    const float bv = beta_v[o];
    const float ba = beta_a[o];
    const __half2* vbase = sm.votes + o * 8 + pg * 2;
    const float* rpo = sm.rpT + o * RST;
    __syncthreads();   // rp + votes ready

    for (int it = 0; it < 3; ++it) {
        // ---- M-step: single-pass moments over i-strip ----
        float m0=0.f,m1=0.f,m2=0.f,m3=0.f;
        float s0=0.f,s1=0.f,s2=0.f,s3=0.f;
        float rs=0.f;
        #pragma unroll 6
        for (int ii = 0; ii < 18; ++ii) {
            const int i = c + (ii << 3);
            float rp = rpo[i];
            uint2 hv = *reinterpret_cast<const uint2*>(vbase + i * VSH2);
            float2 f01 = __half22float2(*reinterpret_cast<__half2*>(&hv.x));
            float2 f23 = __half22float2(*reinterpret_cast<__half2*>(&hv.y));
            float tx = rp * f01.x, ty = rp * f01.y;
            float tz = rp * f23.x, tw = rp * f23.y;
            m0 += tx;  s0 = fmaf(tx, f01.x, s0);
            m1 += ty;  s1 = fmaf(ty, f01.y, s1);
            m2 += tz;  s2 = fmaf(tz, f23.x, s2);
            m3 += tw;  s3 = fmaf(tw, f23.y, s3);
            rs += rp;
        }
        // reduce over c (8 chunks): offsets 4, 8, 16
        #pragma unroll
        for (int off = 4; off < 32; off <<= 1) {
            m0 += __shfl_xor_sync(0xffffffffu, m0, off);
            m1 += __shfl_xor_sync(0xffffffffu, m1, off);
            m2 += __shfl_xor_sync(0xffffffffu, m2, off);
            m3 += __shfl_xor_sync(0xffffffffu, m3, off);
            s0 += __shfl_xor_sync(0xffffffffu, s0, off);
            s1 += __shfl_xor_sync(0xffffffffu, s1, off);
            s2 += __shfl_xor_sync(0xffffffffu, s2, off);
            s3 += __shfl_xor_sync(0xffffffffu, s3, off);
            rs += __shfl_xor_sync(0xffffffffu, rs, off);
        }
        const float inv_r = __fdividef(1.0f, rs + EPSF);
        const float me0 = m0 * inv_r, me1 = m1 * inv_r;
        const float me2 = m2 * inv_r, me3 = m3 * inv_r;
        float e0 = fmaf(me0, fmaf(me0, rs, -2.0f * m0), s0);
        float e1 = fmaf(me1, fmaf(me1, rs, -2.0f * m1), s1);
        float e2 = fmaf(me2, fmaf(me2, rs, -2.0f * m2), s2);
        float e3 = fmaf(me3, fmaf(me3, rs, -2.0f * m3), s3);
        float v0 = fmaxf(e0, 0.f) * inv_r, v1 = fmaxf(e1, 0.f) * inv_r;
        float v2 = fmaxf(e2, 0.f) * inv_r, v3 = fmaxf(e3, 0.f) * inv_r;
        float l4 = (__logf(sqrtf(v0) + EPSF) + __logf(sqrtf(v1) + EPSF))
                 + (__logf(sqrtf(v2) + EPSF) + __logf(sqrtf(v3) + EPSF));
        // reduce over pg (4 groups): offsets 1, 2
        float lsum = l4;
        lsum += __shfl_xor_sync(0xffffffffu, lsum, 1);
        lsum += __shfl_xor_sync(0xffffffffu, lsum, 2);

        const float inv_temp = 1.0f + (float)it;
        const float cost = fmaf(16.0f, bv, lsum) * rs;
        const float a = __fdividef(1.0f, 1.0f + __expf(-inv_temp * (ba - cost)));

        if (it == 2) {
            if (c == 0) {   // lanes 0-3: pg 0..3 -> coalesced 64B
                *reinterpret_cast<float4*>(out + n * 256 + o * 16 + pg * 4) =
                    make_float4(me0, me1, me2, me3);
            }
            if (lane == 0)
                out[NPOS * 256 + n * OSZ + o] = a;
            return;
        }

        const float iv0 = __fdividef(1.0f, 2.0f * v0 + EPSF);
        const float iv1 = __fdividef(1.0f, 2.0f * v1 + EPSF);
        const float iv2 = __fdividef(1.0f, 2.0f * v2 + EPSF);
        const float iv3 = __fdividef(1.0f, 2.0f * v3 + EPSF);
        const float zc  = __logf(a + EPSF) - lsum;     // z = zc - distance

        // ---- E-step part 1: distances from this warp's own strip ----
        #pragma unroll 3
        for (int ii = 0; ii < 18; ++ii) {
            const int i = c + (ii << 3);
            uint2 hv = *reinterpret_cast<const uint2*>(vbase + i * VSH2);
            float2 f01 = __half22float2(*reinterpret_cast<__half2*>(&hv.x));
            float2 f23 = __half22float2(*reinterpret_cast<__half2*>(&hv.y));
            float dx = f01.x - me0, dy = f01.y - me1;
            float dz = f23.x - me2, dw = f23.y - me3;
            float acc = dx * dx * iv0;
            acc = fmaf(dy * dy, iv1, acc);
            acc = fmaf(dz * dz, iv2, acc);
            acc = fmaf(dw * dw, iv3, acc);
            acc += __shfl_xor_sync(0xffffffffu, acc, 1);
            acc += __shfl_xor_sync(0xffffffffu, acc, 2);    // sum over 16 p
            if (pg == 0)
                sm.zS[o * RST + i] = zc - acc;
        }
        __syncthreads();   // z ready

        // ---- E-step part 2: softmax over o, fold act -> rp ----
        if (tid < 2 * ISZ) {
            const int i  = tid >> 1;
            const int g2 = tid & 1;
            float zz[8];
            float zmax = -1e30f;
            #pragma unroll
            for (int j = 0; j < 8; ++j) {
                float z = sm.zS[((j << 1) + g2) * RST + i];
                zz[j] = z;
                zmax = fmaxf(zmax, z);
            }
            zmax = fmaxf(zmax, __shfl_xor_sync(0xffffffffu, zmax, 1));
            float es = 0.f;
            #pragma unroll
            for (int j = 0; j < 8; ++j) { zz[j] = __expf(zz[j] - zmax); es += zz[j]; }
            es += __shfl_xor_sync(0xffffffffu, es, 1);
            const float f = __fdividef(sm.actS[i], es);   // softmax * act
            #pragma unroll
            for (int j = 0; j < 8; ++j)
                sm.rpT[((j << 1) + g2) * RST + i] = zz[j] * f;
        }
        __syncthreads();   // rp ready for next M-step
    }
}

extern "C" void kernel_launch(void* const* d_in, const int* in_sizes, int n_in,
                              void* d_out, int out_size)
{
    const float* pose_in = (const float*)d_in[0];
    const float* act_in  = (const float*)d_in[1];
    const float* w       = (const float*)d_in[2];
    const float* bv      = (const float*)d_in[3];
    const float* ba      = (const float*)d_in[4];
    float* out           = (float*)d_out;

    const int smem = (int)sizeof(Smem);
    cudaFuncSetAttribute(capsconv_em_kernel,
                         cudaFuncAttributeMaxDynamicSharedMemorySize, smem);
    capsconv_em_kernel<<<NPOS, 512, smem>>>(pose_in, act_in, w, bv, ba, out);
}